// round 12
// baseline (speedup 1.0000x reference)
#include <cuda_runtime.h>
#define HW 65536
#define NB 4
typedef unsigned long long ull;

// canonical ch order: 0..127 kv1(x1), 128..191 q2(x1), 192..255 q1(y1), 256..383 kv2(y1)
__device__ __align__(16) float g_pre [(size_t)NB * 384 * HW];
__device__ __align__(16) float g_postv[(size_t)NB * 128 * HW];   // 0..63 v1, 64..127 v2
__device__ __align__(16) float g_W1f [64 * 384];   // [k][oc'] plain float
__device__ __align__(16) float g_W5f [8 * 64 * 64];  // [stage][k][oc] plain float
__device__ __align__(16) float g_PoFf[8 * 64 * 64];  // [(br*4+b)][k=vch][oc] plain float
__device__ float g_S [8 * 8 * 64];
__device__ float g_sq[8 * 2 * 64];

__device__ __forceinline__ ull pack2(float a) {
    ull r; asm("mov.b64 %0,{%1,%1};" : "=l"(r) : "f"(a)); return r;
}
__device__ __forceinline__ void ffma2(ull& acc, ull a, ull b) {
    asm("fma.rn.f32x2 %0,%1,%2,%0;" : "+l"(acc) : "l"(a), "l"(b));
}
__device__ __forceinline__ float2 unpack2(ull v) {
    float2 f; asm("mov.b64 {%0,%1},%2;" : "=f"(f.x), "=f"(f.y) : "l"(v)); return f;
}
__device__ __forceinline__ float warp_red(float v) {
    #pragma unroll
    for (int o = 16; o; o >>= 1) v += __shfl_xor_sync(0xffffffffu, v, o);
    return v;
}

// ---------------- prep kernels (3, so k1 is the profiled 4th launch) ----------
__global__ void k_prep_a(const float* __restrict__ kv1w, const float* __restrict__ q1w,
                         const float* __restrict__ kv2w, const float* __restrict__ q2w)
{
    int e = blockIdx.x * 256 + threadIdx.x;
    if (e < 24576) {
        int oc = e % 384, k = e / 384;
        float w;
        if      (oc < 128) w = kv1w[oc * 64 + k];
        else if (oc < 192) w = q2w [(oc - 128) * 64 + k];
        else if (oc < 256) w = q1w [(oc - 192) * 64 + k];
        else               w = kv2w[(oc - 256) * 64 + k];
        g_W1f[e] = w;
    }
}
__global__ void k_prep_b(const float* __restrict__ mm1w, const float* __restrict__ mm2w)
{
    int e = blockIdx.x * 256 + threadIdx.x;
    if (e < 32768) {
        int s = e >> 12, rem = e & 4095, k = rem >> 6, oc = rem & 63;
        const float* src = (s < 4 ? mm1w : mm2w) + (s & 3) * 4096;
        g_W5f[e] = src[oc * 64 + k];
    }
}
__global__ void k_prep_c()
{
    int e = blockIdx.x * 256 + threadIdx.x;
    if (e < 4096) g_S[e] = 0.f;
    if (e < 1024) g_sq[e] = 0.f;
}

// ---------------- K1: LN + pointwise projections (profiled slot, 366us) --------
// 64px strips, 4oc x 4px thread tile. Plain-float weights (16KB) -> smem 32.5KB, occ 5.
__global__ __launch_bounds__(256, 5) void k1_pointwise(
    const float* __restrict__ x, const float* __restrict__ y,
    const float* __restrict__ lnw, const float* __restrict__ lnb)
{
    extern __shared__ __align__(16) float smf[];
    float* Ws  = smf;           // [64k][64oc] plain = 16KB
    float* act = smf + 4096;    // [64c][64px] = 16KB
    float* lnp = smf + 8192;    // 128

    int tid = threadIdx.x;
    int p0  = blockIdx.x * 64;
    int s   = blockIdx.y;       // 0,1=kv1 2=q2 (x1); 3=q1 4,5=kv2 (y1)
    int b   = blockIdx.z;

    const float* in0 = (s < 3 ? x : y) + (size_t)b * 64 * HW + p0;
    #pragma unroll
    for (int i = 0; i < 16; i++) {
        int idx = tid + i * 256;
        act[idx] = in0[(size_t)(idx >> 6) * HW + (idx & 63)];
    }
    if (tid < 64) { lnp[tid] = lnw[tid]; lnp[64 + tid] = lnb[tid]; }
    #pragma unroll
    for (int i = 0; i < 16; i++) {
        int idx = tid + i * 256;
        Ws[idx] = g_W1f[(idx >> 6) * 384 + s * 64 + (idx & 63)];
    }
    __syncthreads();

    if (tid < 64) {
        int p = tid;
        float sum = 0.f, s2 = 0.f;
        #pragma unroll
        for (int c = 0; c < 64; c++) { float v = act[c * 64 + p]; sum += v; s2 += v * v; }
        float mu  = sum * (1.f / 64.f);
        float var = s2 * (1.f / 64.f) - mu * mu;
        float r = rsqrtf(var + 1e-5f);
        #pragma unroll
        for (int c = 0; c < 64; c++)
            act[c * 64 + p] = (act[c * 64 + p] - mu) * r * lnp[c] + lnp[64 + c];
    }
    __syncthreads();

    int px0 = (tid & 15) * 4, oc0 = (tid >> 4) * 4;
    ull acc[4][2];
    #pragma unroll
    for (int i = 0; i < 4; i++) { acc[i][0] = 0ull; acc[i][1] = 0ull; }

    #pragma unroll 4
    for (int k = 0; k < 64; k++) {
        ulonglong2 xv = *(const ulonglong2*)(act + k * 64 + px0);
        float4 wf = *(const float4*)(Ws + k * 64 + oc0);
        ull w0 = pack2(wf.x), w1 = pack2(wf.y), w2 = pack2(wf.z), w3 = pack2(wf.w);
        ffma2(acc[0][0], w0, xv.x); ffma2(acc[0][1], w0, xv.y);
        ffma2(acc[1][0], w1, xv.x); ffma2(acc[1][1], w1, xv.y);
        ffma2(acc[2][0], w2, xv.x); ffma2(acc[2][1], w2, xv.y);
        ffma2(acc[3][0], w3, xv.x); ffma2(acc[3][1], w3, xv.y);
    }
    float* ob = g_pre + ((size_t)b * 384 + s * 64) * HW + p0;
    #pragma unroll
    for (int i = 0; i < 4; i++) {
        ulonglong2 v; v.x = acc[i][0]; v.y = acc[i][1];
        *(ulonglong2*)(ob + (size_t)(oc0 + i) * HW + px0) = v;
    }
}

// ---------------- kA: fused dwconv(q,k) + attention stats (229us measured) -----
__device__ __forceinline__ float conv1(const float* t, const float* wp, int row, int lane)
{
    float a = 0.f;
    #pragma unroll
    for (int dr = 0; dr < 3; dr++) {
        const float* r = t + (row + dr) * 34 + lane;
        a += wp[dr * 3] * r[0] + wp[dr * 3 + 1] * r[1] + wp[dr * 3 + 2] * r[2];
    }
    return a;
}

__global__ __launch_bounds__(256, 2) void kA_stats(
    const float* __restrict__ kvdw1, const float* __restrict__ qdw1,
    const float* __restrict__ kvdw2, const float* __restrict__ qdw2)
{
    __shared__ __align__(16) float tile[16 * 340];  // 16ch x 10r x 34c
    __shared__ float w9s[144];
    __shared__ int chtab[16];

    int tid = threadIdx.x;
    int z = blockIdx.z;
    int h = z & 7, br = (z >> 3) & 1, b = z >> 4;
    int c0 = blockIdx.x * 32;
    int r0b = blockIdx.y * 64;
    int qbase = (br ? 128 : 192) + 8 * h;
    int kbase = (br ? 256 :   0) + 8 * h;

    if (tid < 16)
        chtab[tid] = tid < 8 ? qbase + tid : kbase + tid - 8;
    if (tid < 144) {
        int ci = tid / 9, t = tid - ci * 9;
        int chg = ci < 8 ? qbase + ci : kbase + ci - 8;
        const float* ws;
        if      (chg < 128) ws = kvdw1 + chg * 9;
        else if (chg < 192) ws = qdw2 + (chg - 128) * 9;
        else if (chg < 256) ws = qdw1 + (chg - 192) * 9;
        else                ws = kvdw2 + (chg - 256) * 9;
        w9s[tid] = ws[t];
    }

    float S[64], q[8], qs[8], ks[8];
    #pragma unroll
    for (int i = 0; i < 64; i++) S[i] = 0.f;
    #pragma unroll
    for (int i = 0; i < 8; i++) { qs[i] = 0.f; ks[i] = 0.f; }

    int w = tid >> 5, lane = tid & 31;
    int row = w;

    for (int it = 0; it < 8; it++) {
        int r0 = r0b + it * 8;
        __syncthreads();
        #pragma unroll
        for (int cc2 = 0; cc2 < 2; cc2++) {
            int ci = w * 2 + cc2;
            const float* gp = g_pre + ((size_t)b * 384 + chtab[ci]) * HW;
            float* trow = tile + ci * 340;
            #pragma unroll
            for (int r = 0; r < 10; r++) {
                int gr = r0 + r - 1;
                bool rok = (unsigned)gr < 256u;
                float v0 = 0.f, v1 = 0.f;
                int gc0 = c0 + lane - 1;
                int gc1 = c0 + 31 + lane;
                if (rok && (unsigned)gc0 < 256u) v0 = gp[gr * 256 + gc0];
                if (lane < 2 && rok && (unsigned)gc1 < 256u) v1 = gp[gr * 256 + gc1];
                trow[r * 34 + lane] = v0;
                if (lane < 2) trow[r * 34 + 32 + lane] = v1;
            }
        }
        __syncthreads();

        #pragma unroll
        for (int i = 0; i < 8; i++) {
            q[i] = conv1(tile + i * 340, w9s + i * 9, row, lane);
            qs[i] += q[i] * q[i];
        }
        #pragma unroll
        for (int j = 0; j < 8; j++) {
            float kv = conv1(tile + (8 + j) * 340, w9s + (8 + j) * 9, row, lane);
            ks[j] += kv * kv;
            #pragma unroll
            for (int i = 0; i < 8; i++)
                S[i * 8 + j] += q[i] * kv;
        }
    }

    __syncthreads();
    #pragma unroll
    for (int i = 0; i < 64; i++) {
        float v = warp_red(S[i]);
        if (!lane) tile[i * 8 + w] = v;
    }
    #pragma unroll
    for (int i = 0; i < 8; i++) {
        float v = warp_red(qs[i]); if (!lane) tile[512 + i * 8 + w] = v;
        v = warp_red(ks[i]);       if (!lane) tile[576 + i * 8 + w] = v;
    }
    __syncthreads();
    size_t sb = ((size_t)(br * 4 + b) * 8 + h) * 64;
    size_t qb = ((size_t)(br * 4 + b) * 2) * 64 + h * 8;
    if (tid < 64) {
        float s = 0.f;
        #pragma unroll
        for (int j = 0; j < 8; j++) s += tile[tid * 8 + j];
        atomicAdd(&g_S[sb + tid], s);
    } else if (tid < 72) {
        int i = tid - 64; float s = 0.f;
        #pragma unroll
        for (int j = 0; j < 8; j++) s += tile[512 + i * 8 + j];
        atomicAdd(&g_sq[qb + i], s);
    } else if (tid < 80) {
        int i = tid - 72; float s = 0.f;
        #pragma unroll
        for (int j = 0; j < 8; j++) s += tile[576 + i * 8 + j];
        atomicAdd(&g_sq[qb + 64 + i], s);
    }
}

// ---------------- k_dwv: depthwise 3x3 for v channels (46us measured) ----------
__global__ __launch_bounds__(256) void k_dwv(const float* __restrict__ kvdw1,
                                             const float* __restrict__ kvdw2)
{
    __shared__ __align__(16) float s[18 * 264];
    int tid = threadIdx.x;
    int r0 = blockIdx.x * 16;
    int vc = blockIdx.y;
    int b  = blockIdx.z;
    int srcpl = vc < 64 ? 64 + vc : 256 + vc;
    const float* w9 = vc < 64 ? kvdw1 + (64 + vc) * 9 : kvdw2 + vc * 9;
    float w[9];
    #pragma unroll
    for (int t = 0; t < 9; t++) w[t] = __ldg(w9 + t);

    const float* in = g_pre + ((size_t)b * 384 + srcpl) * HW;
    #pragma unroll
    for (int r = 0; r < 18; r++) {
        int gr = r0 + r - 1;
        float v = ((unsigned)gr < 256u) ? in[gr * 256 + tid] : 0.f;
        s[r * 264 + 1 + tid] = v;
        if (tid < 2) s[r * 264 + tid * 257] = 0.f;
    }
    __syncthreads();

    float* out = g_postv + ((size_t)b * 128 + vc) * HW + r0 * 256 + tid;
    float a00 = s[tid], a01 = s[tid + 1], a02 = s[tid + 2];
    float a10 = s[264 + tid], a11 = s[264 + tid + 1], a12 = s[264 + tid + 2];
    #pragma unroll
    for (int i = 0; i < 16; i++) {
        const float* rw = s + (i + 2) * 264 + tid;
        float b0 = rw[0], b1 = rw[1], b2 = rw[2];
        float acc = w[0] * a00 + w[1] * a01 + w[2] * a02
                  + w[3] * a10 + w[4] * a11 + w[5] * a12
                  + w[6] * b0  + w[7] * b1  + w[8] * b2;
        out[i * 256] = acc;
        a00 = a10; a01 = a11; a02 = a12;
        a10 = b0;  a11 = b1;  a12 = b2;
    }
}

// ---------------- k4: softmax + fold po @ blockdiag(A), plain-float out --------
__global__ void k4_fold(const float* __restrict__ temp,
                        const float* __restrict__ po1, const float* __restrict__ po2)
{
    int br = blockIdx.x & 1, b = blockIdx.x >> 1;
    __shared__ float A[8][8][8];
    __shared__ float nq[64], nk[64];
    int t = threadIdx.x;  // 0..63
    {
        size_t qb = ((size_t)(br * 4 + b) * 2) * 64;
        nq[t] = fmaxf(sqrtf(g_sq[qb + t]), 1e-12f);
        nk[t] = fmaxf(sqrtf(g_sq[qb + 64 + t]), 1e-12f);
    }
    __syncthreads();
    {
        int h = t >> 3, c = t & 7;
        float tp = temp[h];
        const float* Srow = g_S + ((size_t)(br * 4 + b) * 8 + h) * 64 + c * 8;
        float v[8], mx = -1e30f;
        #pragma unroll
        for (int d = 0; d < 8; d++) {
            v[d] = Srow[d] / (nq[h * 8 + c] * nk[h * 8 + d]) * tp;
            mx = fmaxf(mx, v[d]);
        }
        float sum = 0.f;
        #pragma unroll
        for (int d = 0; d < 8; d++) { v[d] = expf(v[d] - mx); sum += v[d]; }
        float inv = 1.f / sum;
        #pragma unroll
        for (int d = 0; d < 8; d++) A[h][c][d] = v[d] * inv;
    }
    __syncthreads();
    const float* po = br ? po2 : po1;
    for (int hd = 0; hd < 64; hd++) {
        int h = hd >> 3, d = hd & 7;
        float s = 0.f;
        #pragma unroll
        for (int c = 0; c < 8; c++) s += po[t * 64 + h * 8 + c] * A[h][c][d];
        g_PoFf[(size_t)(br * 4 + b) * 4096 + hd * 64 + t] = s;  // [k=hd][oc=t]
    }
}

// ---------------- K5: modulation MLP + folded projection + residual ----------
// Scale `s` lives in 16 registers per thread (same thread produces & consumes it).
// smem = inp + vT + h1 = 48KB -> occ 4.
// MODE 0: lrelu(acc+b)->dst ; 1: acc+b->sreg ; 2: vmod = vmod*(sreg+1)+(acc+b) ;
// MODE 3: outg = acc + resg
template <int MODE>
__device__ __forceinline__ void stageP(const float* __restrict__ Wg, const float* __restrict__ bg,
                                       const float* __restrict__ src, float* dst,
                                       float* sreg, float* vmod,
                                       const float* resg, float* outg, int tid)
{
    int px0 = (tid & 15) * 4, oc0 = (tid >> 4) * 4;
    ull acc[4][2];
    #pragma unroll
    for (int i = 0; i < 4; i++) { acc[i][0] = 0ull; acc[i][1] = 0ull; }

    #pragma unroll 4
    for (int k = 0; k < 64; k++) {
        ulonglong2 xv = *(const ulonglong2*)(src + k * 64 + px0);
        float4 wf = __ldg((const float4*)(Wg + k * 64 + oc0));
        ull w0 = pack2(wf.x), w1 = pack2(wf.y), w2 = pack2(wf.z), w3 = pack2(wf.w);
        ffma2(acc[0][0], w0, xv.x); ffma2(acc[0][1], w0, xv.y);
        ffma2(acc[1][0], w1, xv.x); ffma2(acc[1][1], w1, xv.y);
        ffma2(acc[2][0], w2, xv.x); ffma2(acc[2][1], w2, xv.y);
        ffma2(acc[3][0], w3, xv.x); ffma2(acc[3][1], w3, xv.y);
    }
    float bb[4] = {0.f, 0.f, 0.f, 0.f};
    if (MODE < 3) { float4 bf = __ldg((const float4*)(bg + oc0));
                    bb[0] = bf.x; bb[1] = bf.y; bb[2] = bf.z; bb[3] = bf.w; }
    #pragma unroll
    for (int i = 0; i < 4; i++) {
        float2 v0 = unpack2(acc[i][0]), v1 = unpack2(acc[i][1]);
        float4 r; r.x = v0.x + bb[i]; r.y = v0.y + bb[i];
                  r.z = v1.x + bb[i]; r.w = v1.y + bb[i];
        int idx = (oc0 + i) * 64 + px0;
        if (MODE == 0) {
            r.x = r.x > 0.f ? r.x : 0.1f * r.x;
            r.y = r.y > 0.f ? r.y : 0.1f * r.y;
            r.z = r.z > 0.f ? r.z : 0.1f * r.z;
            r.w = r.w > 0.f ? r.w : 0.1f * r.w;
            *(float4*)(dst + idx) = r;
        } else if (MODE == 1) {
            sreg[i * 4 + 0] = r.x; sreg[i * 4 + 1] = r.y;
            sreg[i * 4 + 2] = r.z; sreg[i * 4 + 3] = r.w;
        } else if (MODE == 2) {
            float4 vv = *(const float4*)(vmod + idx);
            vv.x = vv.x * (sreg[i * 4 + 0] + 1.f) + r.x;
            vv.y = vv.y * (sreg[i * 4 + 1] + 1.f) + r.y;
            vv.z = vv.z * (sreg[i * 4 + 2] + 1.f) + r.z;
            vv.w = vv.w * (sreg[i * 4 + 3] + 1.f) + r.w;
            *(float4*)(vmod + idx) = vv;
        } else {
            float4 rr = __ldg((const float4*)(resg + (size_t)(oc0 + i) * HW + px0));
            r.x += rr.x; r.y += rr.y; r.z += rr.z; r.w += rr.w;
            *(float4*)(outg + (size_t)(oc0 + i) * HW + px0) = r;
        }
    }
}

__global__ __launch_bounds__(256, 4) void k5_final(
    const float* __restrict__ x, const float* __restrict__ y,
    const float* __restrict__ mm1b, const float* __restrict__ mm2b,
    float* __restrict__ out)
{
    extern __shared__ __align__(16) float sm[];
    float* inp = sm;
    float* vT  = sm + 4096;
    float* h1  = sm + 8192;

    int tid = threadIdx.x;
    int b   = blockIdx.x >> 10;
    int p0  = (blockIdx.x & 1023) << 6;

    float sreg[16];

    const float* xb = x + (size_t)b * 64 * HW + p0;
    const float* yb = y + (size_t)b * 64 * HW + p0;
    const float* va = g_postv + ((size_t)b * 128) * HW + p0;
    #pragma unroll
    for (int i = 0; i < 16; i++) {
        int idx = tid + i * 256; int c = idx >> 6, p = idx & 63;
        size_t g = (size_t)c * HW + p;
        inp[c * 64 + p] = xb[g]; vT[c * 64 + p] = va[g];
    }
    __syncthreads();
    float* out1 = out + (size_t)b * 64 * HW + p0;
    float* out2 = out + (size_t)(NB + b) * 64 * HW + p0;

    // branch 1 (mod input x, residual y, v1, PoF1)
    stageP<0>(g_W5f,         mm1b,       inp, h1, 0, 0, 0, 0, tid);    __syncthreads();
    stageP<1>(g_W5f + 4096,  mm1b + 64,  h1,  0, sreg, 0, 0, 0, tid);  __syncthreads();
    stageP<0>(g_W5f + 8192,  mm1b + 128, inp, h1, 0, 0, 0, 0, tid);    __syncthreads();
    stageP<2>(g_W5f + 12288, mm1b + 192, h1, 0, sreg, vT, 0, 0, tid);  __syncthreads();
    stageP<3>(g_PoFf + (size_t)b * 4096, 0, vT, 0, 0, 0, yb, out1, tid);
    __syncthreads();

    const float* vb2 = g_postv + ((size_t)b * 128 + 64) * HW + p0;
    #pragma unroll
    for (int i = 0; i < 16; i++) {
        int idx = tid + i * 256; int c = idx >> 6, p = idx & 63;
        size_t g = (size_t)c * HW + p;
        inp[c * 64 + p] = yb[g]; vT[c * 64 + p] = vb2[g];
    }
    __syncthreads();

    // branch 2 (mod input y, residual x, v2, PoF2)
    stageP<0>(g_W5f + 16384, mm2b,       inp, h1, 0, 0, 0, 0, tid);    __syncthreads();
    stageP<1>(g_W5f + 20480, mm2b + 64,  h1,  0, sreg, 0, 0, 0, tid);  __syncthreads();
    stageP<0>(g_W5f + 24576, mm2b + 128, inp, h1, 0, 0, 0, 0, tid);    __syncthreads();
    stageP<2>(g_W5f + 28672, mm2b + 192, h1, 0, sreg, vT, 0, 0, tid);  __syncthreads();
    stageP<3>(g_PoFf + (size_t)(4 + b) * 4096, 0, vT, 0, 0, 0, xb, out2, tid);
}

// ---------------- launch ----------------
extern "C" void kernel_launch(void* const* d_in, const int* in_sizes, int n_in,
                              void* d_out, int out_size)
{
    const float* x     = (const float*)d_in[0];
    const float* y     = (const float*)d_in[1];
    const float* lnw   = (const float*)d_in[2];
    const float* lnb   = (const float*)d_in[3];
    const float* temp  = (const float*)d_in[4];
    const float* kv1w  = (const float*)d_in[5];
    const float* kvdw1 = (const float*)d_in[6];
    const float* q1w   = (const float*)d_in[7];
    const float* qdw1  = (const float*)d_in[8];
    const float* po1   = (const float*)d_in[9];
    const float* kv2w  = (const float*)d_in[10];
    const float* kvdw2 = (const float*)d_in[11];
    const float* q2w   = (const float*)d_in[12];
    const float* qdw2  = (const float*)d_in[13];
    const float* po2   = (const float*)d_in[14];
    const float* mm1w  = (const float*)d_in[15];
    const float* mm1b  = (const float*)d_in[16];
    const float* mm2w  = (const float*)d_in[17];
    const float* mm2b  = (const float*)d_in[18];
    float* out = (float*)d_out;

    cudaFuncSetAttribute(k1_pointwise, cudaFuncAttributeMaxDynamicSharedMemorySize, 33280);
    cudaFuncSetAttribute(k5_final,     cudaFuncAttributeMaxDynamicSharedMemorySize, 49152);

    k_prep_a<<<96, 256>>>(kv1w, q1w, kv2w, q2w);
    k_prep_b<<<128, 256>>>(mm1w, mm2w);
    k_prep_c<<<16, 256>>>();
    k1_pointwise<<<dim3(1024, 6, NB), 256, 33280>>>(x, y, lnw, lnb);   // profiled
    kA_stats<<<dim3(8, 4, 64), 256>>>(kvdw1, qdw1, kvdw2, qdw2);
    k_dwv<<<dim3(16, 128, NB), 256>>>(kvdw1, kvdw2);
    k4_fold<<<8, 64>>>(temp, po1, po2);
    k5_final<<<4096, 256, 49152>>>(x, y, mm1b, mm2b, out);
}

// round 13
// speedup vs baseline: 1.0641x; 1.0641x over previous
#include <cuda_runtime.h>
#define HW 65536
#define NB 4
typedef unsigned long long ull;

// canonical ch order: 0..127 kv1(x1), 128..191 q2(x1), 192..255 q1(y1), 256..383 kv2(y1)
__device__ __align__(16) float g_pre [(size_t)NB * 384 * HW];
__device__ __align__(16) float g_postv[(size_t)NB * 128 * HW];   // 0..63 v1, 64..127 v2
__device__ __align__(16) float g_W1f [64 * 384];   // [k][oc'] plain float
__device__ __align__(16) float g_W5f [8 * 64 * 64];  // [stage][k][oc] plain float
__device__ __align__(16) float g_PoFf[8 * 64 * 64];  // [(br*4+b)][k=vch][oc] plain float
__device__ float g_S [8 * 8 * 64];
__device__ float g_sq[8 * 2 * 64];

__device__ __forceinline__ ull pack2(float a) {
    ull r; asm("mov.b64 %0,{%1,%1};" : "=l"(r) : "f"(a)); return r;
}
__device__ __forceinline__ void ffma2(ull& acc, ull a, ull b) {
    asm("fma.rn.f32x2 %0,%1,%2,%0;" : "+l"(acc) : "l"(a), "l"(b));
}
__device__ __forceinline__ float2 unpack2(ull v) {
    float2 f; asm("mov.b64 {%0,%1},%2;" : "=f"(f.x), "=f"(f.y) : "l"(v)); return f;
}
__device__ __forceinline__ float warp_red(float v) {
    #pragma unroll
    for (int o = 16; o; o >>= 1) v += __shfl_xor_sync(0xffffffffu, v, o);
    return v;
}

// ---------------- prep kernels (3, so k1 is the profiled 4th launch) ----------
__global__ void k_prep_a(const float* __restrict__ kv1w, const float* __restrict__ q1w,
                         const float* __restrict__ kv2w, const float* __restrict__ q2w)
{
    int e = blockIdx.x * 256 + threadIdx.x;
    if (e < 24576) {
        int oc = e % 384, k = e / 384;
        float w;
        if      (oc < 128) w = kv1w[oc * 64 + k];
        else if (oc < 192) w = q2w [(oc - 128) * 64 + k];
        else if (oc < 256) w = q1w [(oc - 192) * 64 + k];
        else               w = kv2w[(oc - 256) * 64 + k];
        g_W1f[e] = w;
    }
}
__global__ void k_prep_b(const float* __restrict__ mm1w, const float* __restrict__ mm2w)
{
    int e = blockIdx.x * 256 + threadIdx.x;
    if (e < 32768) {
        int s = e >> 12, rem = e & 4095, k = rem >> 6, oc = rem & 63;
        const float* src = (s < 4 ? mm1w : mm2w) + (s & 3) * 4096;
        g_W5f[e] = src[oc * 64 + k];
    }
}
__global__ void k_prep_c()
{
    int e = blockIdx.x * 256 + threadIdx.x;
    if (e < 4096) g_S[e] = 0.f;
    if (e < 1024) g_sq[e] = 0.f;
}

// ---------------- K1: LN + pointwise projections (profiled slot, 366us) --------
// 64px strips, 4oc x 4px thread tile. Plain-float weights (16KB) -> smem 32.5KB, occ 5.
__global__ __launch_bounds__(256, 5) void k1_pointwise(
    const float* __restrict__ x, const float* __restrict__ y,
    const float* __restrict__ lnw, const float* __restrict__ lnb)
{
    extern __shared__ __align__(16) float smf[];
    float* Ws  = smf;           // [64k][64oc] plain = 16KB
    float* act = smf + 4096;    // [64c][64px] = 16KB
    float* lnp = smf + 8192;    // 128

    int tid = threadIdx.x;
    int p0  = blockIdx.x * 64;
    int s   = blockIdx.y;       // 0,1=kv1 2=q2 (x1); 3=q1 4,5=kv2 (y1)
    int b   = blockIdx.z;

    const float* in0 = (s < 3 ? x : y) + (size_t)b * 64 * HW + p0;
    #pragma unroll
    for (int i = 0; i < 16; i++) {
        int idx = tid + i * 256;
        act[idx] = in0[(size_t)(idx >> 6) * HW + (idx & 63)];
    }
    if (tid < 64) { lnp[tid] = lnw[tid]; lnp[64 + tid] = lnb[tid]; }
    #pragma unroll
    for (int i = 0; i < 16; i++) {
        int idx = tid + i * 256;
        Ws[idx] = g_W1f[(idx >> 6) * 384 + s * 64 + (idx & 63)];
    }
    __syncthreads();

    if (tid < 64) {
        int p = tid;
        float sum = 0.f, s2 = 0.f;
        #pragma unroll
        for (int c = 0; c < 64; c++) { float v = act[c * 64 + p]; sum += v; s2 += v * v; }
        float mu  = sum * (1.f / 64.f);
        float var = s2 * (1.f / 64.f) - mu * mu;
        float r = rsqrtf(var + 1e-5f);
        #pragma unroll
        for (int c = 0; c < 64; c++)
            act[c * 64 + p] = (act[c * 64 + p] - mu) * r * lnp[c] + lnp[64 + c];
    }
    __syncthreads();

    int px0 = (tid & 15) * 4, oc0 = (tid >> 4) * 4;
    ull acc[4][2];
    #pragma unroll
    for (int i = 0; i < 4; i++) { acc[i][0] = 0ull; acc[i][1] = 0ull; }

    #pragma unroll 4
    for (int k = 0; k < 64; k++) {
        ulonglong2 xv = *(const ulonglong2*)(act + k * 64 + px0);
        float4 wf = *(const float4*)(Ws + k * 64 + oc0);
        ull w0 = pack2(wf.x), w1 = pack2(wf.y), w2 = pack2(wf.z), w3 = pack2(wf.w);
        ffma2(acc[0][0], w0, xv.x); ffma2(acc[0][1], w0, xv.y);
        ffma2(acc[1][0], w1, xv.x); ffma2(acc[1][1], w1, xv.y);
        ffma2(acc[2][0], w2, xv.x); ffma2(acc[2][1], w2, xv.y);
        ffma2(acc[3][0], w3, xv.x); ffma2(acc[3][1], w3, xv.y);
    }
    float* ob = g_pre + ((size_t)b * 384 + s * 64) * HW + p0;
    #pragma unroll
    for (int i = 0; i < 4; i++) {
        ulonglong2 v; v.x = acc[i][0]; v.y = acc[i][1];
        *(ulonglong2*)(ob + (size_t)(oc0 + i) * HW + px0) = v;
    }
}

// ---------------- kA: fused dwconv(q,k) + attention stats (229us measured) -----
__device__ __forceinline__ float conv1(const float* t, const float* wp, int row, int lane)
{
    float a = 0.f;
    #pragma unroll
    for (int dr = 0; dr < 3; dr++) {
        const float* r = t + (row + dr) * 34 + lane;
        a += wp[dr * 3] * r[0] + wp[dr * 3 + 1] * r[1] + wp[dr * 3 + 2] * r[2];
    }
    return a;
}

__global__ __launch_bounds__(256, 2) void kA_stats(
    const float* __restrict__ kvdw1, const float* __restrict__ qdw1,
    const float* __restrict__ kvdw2, const float* __restrict__ qdw2)
{
    __shared__ __align__(16) float tile[16 * 340];  // 16ch x 10r x 34c
    __shared__ float w9s[144];
    __shared__ int chtab[16];

    int tid = threadIdx.x;
    int z = blockIdx.z;
    int h = z & 7, br = (z >> 3) & 1, b = z >> 4;
    int c0 = blockIdx.x * 32;
    int r0b = blockIdx.y * 64;
    int qbase = (br ? 128 : 192) + 8 * h;
    int kbase = (br ? 256 :   0) + 8 * h;

    if (tid < 16)
        chtab[tid] = tid < 8 ? qbase + tid : kbase + tid - 8;
    if (tid < 144) {
        int ci = tid / 9, t = tid - ci * 9;
        int chg = ci < 8 ? qbase + ci : kbase + ci - 8;
        const float* ws;
        if      (chg < 128) ws = kvdw1 + chg * 9;
        else if (chg < 192) ws = qdw2 + (chg - 128) * 9;
        else if (chg < 256) ws = qdw1 + (chg - 192) * 9;
        else                ws = kvdw2 + (chg - 256) * 9;
        w9s[tid] = ws[t];
    }

    float S[64], q[8], qs[8], ks[8];
    #pragma unroll
    for (int i = 0; i < 64; i++) S[i] = 0.f;
    #pragma unroll
    for (int i = 0; i < 8; i++) { qs[i] = 0.f; ks[i] = 0.f; }

    int w = tid >> 5, lane = tid & 31;
    int row = w;

    for (int it = 0; it < 8; it++) {
        int r0 = r0b + it * 8;
        __syncthreads();
        #pragma unroll
        for (int cc2 = 0; cc2 < 2; cc2++) {
            int ci = w * 2 + cc2;
            const float* gp = g_pre + ((size_t)b * 384 + chtab[ci]) * HW;
            float* trow = tile + ci * 340;
            #pragma unroll
            for (int r = 0; r < 10; r++) {
                int gr = r0 + r - 1;
                bool rok = (unsigned)gr < 256u;
                float v0 = 0.f, v1 = 0.f;
                int gc0 = c0 + lane - 1;
                int gc1 = c0 + 31 + lane;
                if (rok && (unsigned)gc0 < 256u) v0 = gp[gr * 256 + gc0];
                if (lane < 2 && rok && (unsigned)gc1 < 256u) v1 = gp[gr * 256 + gc1];
                trow[r * 34 + lane] = v0;
                if (lane < 2) trow[r * 34 + 32 + lane] = v1;
            }
        }
        __syncthreads();

        #pragma unroll
        for (int i = 0; i < 8; i++) {
            q[i] = conv1(tile + i * 340, w9s + i * 9, row, lane);
            qs[i] += q[i] * q[i];
        }
        #pragma unroll
        for (int j = 0; j < 8; j++) {
            float kv = conv1(tile + (8 + j) * 340, w9s + (8 + j) * 9, row, lane);
            ks[j] += kv * kv;
            #pragma unroll
            for (int i = 0; i < 8; i++)
                S[i * 8 + j] += q[i] * kv;
        }
    }

    __syncthreads();
    #pragma unroll
    for (int i = 0; i < 64; i++) {
        float v = warp_red(S[i]);
        if (!lane) tile[i * 8 + w] = v;
    }
    #pragma unroll
    for (int i = 0; i < 8; i++) {
        float v = warp_red(qs[i]); if (!lane) tile[512 + i * 8 + w] = v;
        v = warp_red(ks[i]);       if (!lane) tile[576 + i * 8 + w] = v;
    }
    __syncthreads();
    size_t sb = ((size_t)(br * 4 + b) * 8 + h) * 64;
    size_t qb = ((size_t)(br * 4 + b) * 2) * 64 + h * 8;
    if (tid < 64) {
        float s = 0.f;
        #pragma unroll
        for (int j = 0; j < 8; j++) s += tile[tid * 8 + j];
        atomicAdd(&g_S[sb + tid], s);
    } else if (tid < 72) {
        int i = tid - 64; float s = 0.f;
        #pragma unroll
        for (int j = 0; j < 8; j++) s += tile[512 + i * 8 + j];
        atomicAdd(&g_sq[qb + i], s);
    } else if (tid < 80) {
        int i = tid - 72; float s = 0.f;
        #pragma unroll
        for (int j = 0; j < 8; j++) s += tile[576 + i * 8 + j];
        atomicAdd(&g_sq[qb + 64 + i], s);
    }
}

// ---------------- k_dwv: depthwise 3x3 for v channels (46us measured) ----------
__global__ __launch_bounds__(256) void k_dwv(const float* __restrict__ kvdw1,
                                             const float* __restrict__ kvdw2)
{
    __shared__ __align__(16) float s[18 * 264];
    int tid = threadIdx.x;
    int r0 = blockIdx.x * 16;
    int vc = blockIdx.y;
    int b  = blockIdx.z;
    int srcpl = vc < 64 ? 64 + vc : 256 + vc;
    const float* w9 = vc < 64 ? kvdw1 + (64 + vc) * 9 : kvdw2 + vc * 9;
    float w[9];
    #pragma unroll
    for (int t = 0; t < 9; t++) w[t] = __ldg(w9 + t);

    const float* in = g_pre + ((size_t)b * 384 + srcpl) * HW;
    #pragma unroll
    for (int r = 0; r < 18; r++) {
        int gr = r0 + r - 1;
        float v = ((unsigned)gr < 256u) ? in[gr * 256 + tid] : 0.f;
        s[r * 264 + 1 + tid] = v;
        if (tid < 2) s[r * 264 + tid * 257] = 0.f;
    }
    __syncthreads();

    float* out = g_postv + ((size_t)b * 128 + vc) * HW + r0 * 256 + tid;
    float a00 = s[tid], a01 = s[tid + 1], a02 = s[tid + 2];
    float a10 = s[264 + tid], a11 = s[264 + tid + 1], a12 = s[264 + tid + 2];
    #pragma unroll
    for (int i = 0; i < 16; i++) {
        const float* rw = s + (i + 2) * 264 + tid;
        float b0 = rw[0], b1 = rw[1], b2 = rw[2];
        float acc = w[0] * a00 + w[1] * a01 + w[2] * a02
                  + w[3] * a10 + w[4] * a11 + w[5] * a12
                  + w[6] * b0  + w[7] * b1  + w[8] * b2;
        out[i * 256] = acc;
        a00 = a10; a01 = a11; a02 = a12;
        a10 = b0;  a11 = b1;  a12 = b2;
    }
}

// ---------------- k4: softmax + fold po @ blockdiag(A), plain-float out --------
__global__ void k4_fold(const float* __restrict__ temp,
                        const float* __restrict__ po1, const float* __restrict__ po2)
{
    int br = blockIdx.x & 1, b = blockIdx.x >> 1;
    __shared__ float A[8][8][8];
    __shared__ float nq[64], nk[64];
    int t = threadIdx.x;  // 0..63
    {
        size_t qb = ((size_t)(br * 4 + b) * 2) * 64;
        nq[t] = fmaxf(sqrtf(g_sq[qb + t]), 1e-12f);
        nk[t] = fmaxf(sqrtf(g_sq[qb + 64 + t]), 1e-12f);
    }
    __syncthreads();
    {
        int h = t >> 3, c = t & 7;
        float tp = temp[h];
        const float* Srow = g_S + ((size_t)(br * 4 + b) * 8 + h) * 64 + c * 8;
        float v[8], mx = -1e30f;
        #pragma unroll
        for (int d = 0; d < 8; d++) {
            v[d] = Srow[d] / (nq[h * 8 + c] * nk[h * 8 + d]) * tp;
            mx = fmaxf(mx, v[d]);
        }
        float sum = 0.f;
        #pragma unroll
        for (int d = 0; d < 8; d++) { v[d] = expf(v[d] - mx); sum += v[d]; }
        float inv = 1.f / sum;
        #pragma unroll
        for (int d = 0; d < 8; d++) A[h][c][d] = v[d] * inv;
    }
    __syncthreads();
    const float* po = br ? po2 : po1;
    for (int hd = 0; hd < 64; hd++) {
        int h = hd >> 3, d = hd & 7;
        float s = 0.f;
        #pragma unroll
        for (int c = 0; c < 8; c++) s += po[t * 64 + h * 8 + c] * A[h][c][d];
        g_PoFf[(size_t)(br * 4 + b) * 4096 + hd * 64 + t] = s;  // [k=hd][oc=t]
    }
}

// ---------------- K5: fused modulation MLP (3 passes/branch) ----------
// Pass A: dual GEMM src -> lrelu(W0*src+b0), lrelu(W2*src+b2)  [16 acc regs]
__device__ __forceinline__ void stageDA(const float* __restrict__ W0, const float* __restrict__ W2,
                                        const float* __restrict__ b0, const float* __restrict__ b2,
                                        const float* __restrict__ src, float* d0, float* d1, int tid)
{
    int px0 = (tid & 15) * 4, oc0 = (tid >> 4) * 4;
    ull a0[4][2], a1[4][2];
    #pragma unroll
    for (int i = 0; i < 4; i++) { a0[i][0] = a0[i][1] = 0ull; a1[i][0] = a1[i][1] = 0ull; }

    #pragma unroll 2
    for (int k = 0; k < 64; k++) {
        ulonglong2 xv = *(const ulonglong2*)(src + k * 64 + px0);
        float4 w0f = __ldg((const float4*)(W0 + k * 64 + oc0));
        float4 w2f = __ldg((const float4*)(W2 + k * 64 + oc0));
        ull p0 = pack2(w0f.x), p1 = pack2(w0f.y), p2 = pack2(w0f.z), p3 = pack2(w0f.w);
        ull q0 = pack2(w2f.x), q1 = pack2(w2f.y), q2 = pack2(w2f.z), q3 = pack2(w2f.w);
        ffma2(a0[0][0], p0, xv.x); ffma2(a0[0][1], p0, xv.y);
        ffma2(a0[1][0], p1, xv.x); ffma2(a0[1][1], p1, xv.y);
        ffma2(a0[2][0], p2, xv.x); ffma2(a0[2][1], p2, xv.y);
        ffma2(a0[3][0], p3, xv.x); ffma2(a0[3][1], p3, xv.y);
        ffma2(a1[0][0], q0, xv.x); ffma2(a1[0][1], q0, xv.y);
        ffma2(a1[1][0], q1, xv.x); ffma2(a1[1][1], q1, xv.y);
        ffma2(a1[2][0], q2, xv.x); ffma2(a1[2][1], q2, xv.y);
        ffma2(a1[3][0], q3, xv.x); ffma2(a1[3][1], q3, xv.y);
    }
    float4 bf0 = __ldg((const float4*)(b0 + oc0));
    float4 bf2 = __ldg((const float4*)(b2 + oc0));
    float bb0[4] = {bf0.x, bf0.y, bf0.z, bf0.w};
    float bb2[4] = {bf2.x, bf2.y, bf2.z, bf2.w};
    #pragma unroll
    for (int i = 0; i < 4; i++) {
        int idx = ((tid >> 4) * 4 + i) * 64 + (tid & 15) * 4;
        float2 u0 = unpack2(a0[i][0]), u1 = unpack2(a0[i][1]);
        float4 r; r.x = u0.x + bb0[i]; r.y = u0.y + bb0[i];
                  r.z = u1.x + bb0[i]; r.w = u1.y + bb0[i];
        r.x = r.x > 0.f ? r.x : 0.1f * r.x;  r.y = r.y > 0.f ? r.y : 0.1f * r.y;
        r.z = r.z > 0.f ? r.z : 0.1f * r.z;  r.w = r.w > 0.f ? r.w : 0.1f * r.w;
        *(float4*)(d0 + idx) = r;
        float2 v0 = unpack2(a1[i][0]), v1 = unpack2(a1[i][1]);
        float4 t; t.x = v0.x + bb2[i]; t.y = v0.y + bb2[i];
                  t.z = v1.x + bb2[i]; t.w = v1.y + bb2[i];
        t.x = t.x > 0.f ? t.x : 0.1f * t.x;  t.y = t.y > 0.f ? t.y : 0.1f * t.y;
        t.z = t.z > 0.f ? t.z : 0.1f * t.z;  t.w = t.w > 0.f ? t.w : 0.1f * t.w;
        *(float4*)(d1 + idx) = t;
    }
}

// Pass B: dual GEMM (srcS->s via W1,b1) (srcT->t via W3,b3); vmod = vmod*(s+1)+t
__device__ __forceinline__ void stageDB(const float* __restrict__ W1, const float* __restrict__ W3,
                                        const float* __restrict__ b1, const float* __restrict__ b3,
                                        const float* __restrict__ srcS, const float* __restrict__ srcT,
                                        float* vmod, int tid)
{
    int px0 = (tid & 15) * 4, oc0 = (tid >> 4) * 4;
    ull aS[4][2], aT[4][2];
    #pragma unroll
    for (int i = 0; i < 4; i++) { aS[i][0] = aS[i][1] = 0ull; aT[i][0] = aT[i][1] = 0ull; }

    #pragma unroll 2
    for (int k = 0; k < 64; k++) {
        ulonglong2 xs = *(const ulonglong2*)(srcS + k * 64 + px0);
        ulonglong2 xt = *(const ulonglong2*)(srcT + k * 64 + px0);
        float4 w1f = __ldg((const float4*)(W1 + k * 64 + oc0));
        float4 w3f = __ldg((const float4*)(W3 + k * 64 + oc0));
        ull p0 = pack2(w1f.x), p1 = pack2(w1f.y), p2 = pack2(w1f.z), p3 = pack2(w1f.w);
        ull q0 = pack2(w3f.x), q1 = pack2(w3f.y), q2 = pack2(w3f.z), q3 = pack2(w3f.w);
        ffma2(aS[0][0], p0, xs.x); ffma2(aS[0][1], p0, xs.y);
        ffma2(aS[1][0], p1, xs.x); ffma2(aS[1][1], p1, xs.y);
        ffma2(aS[2][0], p2, xs.x); ffma2(aS[2][1], p2, xs.y);
        ffma2(aS[3][0], p3, xs.x); ffma2(aS[3][1], p3, xs.y);
        ffma2(aT[0][0], q0, xt.x); ffma2(aT[0][1], q0, xt.y);
        ffma2(aT[1][0], q1, xt.x); ffma2(aT[1][1], q1, xt.y);
        ffma2(aT[2][0], q2, xt.x); ffma2(aT[2][1], q2, xt.y);
        ffma2(aT[3][0], q3, xt.x); ffma2(aT[3][1], q3, xt.y);
    }
    float4 bf1 = __ldg((const float4*)(b1 + oc0));
    float4 bf3 = __ldg((const float4*)(b3 + oc0));
    float bb1[4] = {bf1.x, bf1.y, bf1.z, bf1.w};
    float bb3[4] = {bf3.x, bf3.y, bf3.z, bf3.w};
    #pragma unroll
    for (int i = 0; i < 4; i++) {
        int idx = (oc0 + i) * 64 + px0;
        float2 s0 = unpack2(aS[i][0]), s1 = unpack2(aS[i][1]);
        float2 t0 = unpack2(aT[i][0]), t1 = unpack2(aT[i][1]);
        float4 vv = *(const float4*)(vmod + idx);
        vv.x = vv.x * (s0.x + bb1[i] + 1.f) + (t0.x + bb3[i]);
        vv.y = vv.y * (s0.y + bb1[i] + 1.f) + (t0.y + bb3[i]);
        vv.z = vv.z * (s1.x + bb1[i] + 1.f) + (t1.x + bb3[i]);
        vv.w = vv.w * (s1.y + bb1[i] + 1.f) + (t1.y + bb3[i]);
        *(float4*)(vmod + idx) = vv;
    }
}

// Pass C: out = PoF * vmod + residual
__device__ __forceinline__ void stageC(const float* __restrict__ Wg,
                                       const float* __restrict__ src,
                                       const float* __restrict__ resg, float* outg, int tid)
{
    int px0 = (tid & 15) * 4, oc0 = (tid >> 4) * 4;
    ull acc[4][2];
    #pragma unroll
    for (int i = 0; i < 4; i++) { acc[i][0] = 0ull; acc[i][1] = 0ull; }

    #pragma unroll 4
    for (int k = 0; k < 64; k++) {
        ulonglong2 xv = *(const ulonglong2*)(src + k * 64 + px0);
        float4 wf = __ldg((const float4*)(Wg + k * 64 + oc0));
        ull w0 = pack2(wf.x), w1 = pack2(wf.y), w2 = pack2(wf.z), w3 = pack2(wf.w);
        ffma2(acc[0][0], w0, xv.x); ffma2(acc[0][1], w0, xv.y);
        ffma2(acc[1][0], w1, xv.x); ffma2(acc[1][1], w1, xv.y);
        ffma2(acc[2][0], w2, xv.x); ffma2(acc[2][1], w2, xv.y);
        ffma2(acc[3][0], w3, xv.x); ffma2(acc[3][1], w3, xv.y);
    }
    #pragma unroll
    for (int i = 0; i < 4; i++) {
        float2 v0 = unpack2(acc[i][0]), v1 = unpack2(acc[i][1]);
        size_t gidx = (size_t)(oc0 + i) * HW + px0;
        float4 rr = __ldg((const float4*)(resg + gidx));
        float4 r; r.x = v0.x + rr.x; r.y = v0.y + rr.y;
                  r.z = v1.x + rr.z; r.w = v1.y + rr.w;
        *(float4*)(outg + gidx) = r;
    }
}

__global__ __launch_bounds__(256, 3) void k5_final(
    const float* __restrict__ x, const float* __restrict__ y,
    const float* __restrict__ mm1b, const float* __restrict__ mm2b,
    float* __restrict__ out)
{
    extern __shared__ __align__(16) float sm[];
    float* inp = sm;
    float* h1  = sm + 4096;
    float* h1b = sm + 8192;
    float* vT  = sm + 12288;

    int tid = threadIdx.x;
    int b   = blockIdx.x >> 10;
    int p0  = (blockIdx.x & 1023) << 6;

    const float* xb = x + (size_t)b * 64 * HW + p0;
    const float* yb = y + (size_t)b * 64 * HW + p0;
    const float* va = g_postv + ((size_t)b * 128) * HW + p0;
    #pragma unroll
    for (int i = 0; i < 16; i++) {
        int idx = tid + i * 256; int c = idx >> 6, p = idx & 63;
        size_t g = (size_t)c * HW + p;
        inp[c * 64 + p] = xb[g]; vT[c * 64 + p] = va[g];
    }
    __syncthreads();
    float* out1 = out + (size_t)b * 64 * HW + p0;
    float* out2 = out + (size_t)(NB + b) * 64 * HW + p0;

    // branch 1 (mod input x, residual y, v1, PoF1)
    stageDA(g_W5f, g_W5f + 8192, mm1b, mm1b + 128, inp, h1, h1b, tid);          __syncthreads();
    stageDB(g_W5f + 4096, g_W5f + 12288, mm1b + 64, mm1b + 192, h1, h1b, vT, tid); __syncthreads();
    stageC(g_PoFf + (size_t)b * 4096, vT, yb, out1, tid);
    __syncthreads();

    const float* vb2 = g_postv + ((size_t)b * 128 + 64) * HW + p0;
    #pragma unroll
    for (int i = 0; i < 16; i++) {
        int idx = tid + i * 256; int c = idx >> 6, p = idx & 63;
        size_t g = (size_t)c * HW + p;
        inp[c * 64 + p] = yb[g]; vT[c * 64 + p] = vb2[g];
    }
    __syncthreads();

    // branch 2 (mod input y, residual x, v2, PoF2)
    stageDA(g_W5f + 16384, g_W5f + 24576, mm2b, mm2b + 128, inp, h1, h1b, tid); __syncthreads();
    stageDB(g_W5f + 20480, g_W5f + 28672, mm2b + 64, mm2b + 192, h1, h1b, vT, tid); __syncthreads();
    stageC(g_PoFf + (size_t)(4 + b) * 4096, vT, xb, out2, tid);
}

// ---------------- launch ----------------
extern "C" void kernel_launch(void* const* d_in, const int* in_sizes, int n_in,
                              void* d_out, int out_size)
{
    const float* x     = (const float*)d_in[0];
    const float* y     = (const float*)d_in[1];
    const float* lnw   = (const float*)d_in[2];
    const float* lnb   = (const float*)d_in[3];
    const float* temp  = (const float*)d_in[4];
    const float* kv1w  = (const float*)d_in[5];
    const float* kvdw1 = (const float*)d_in[6];
    const float* q1w   = (const float*)d_in[7];
    const float* qdw1  = (const float*)d_in[8];
    const float* po1   = (const float*)d_in[9];
    const float* kv2w  = (const float*)d_in[10];
    const float* kvdw2 = (const float*)d_in[11];
    const float* q2w   = (const float*)d_in[12];
    const float* qdw2  = (const float*)d_in[13];
    const float* po2   = (const float*)d_in[14];
    const float* mm1w  = (const float*)d_in[15];
    const float* mm1b  = (const float*)d_in[16];
    const float* mm2w  = (const float*)d_in[17];
    const float* mm2b  = (const float*)d_in[18];
    float* out = (float*)d_out;

    cudaFuncSetAttribute(k1_pointwise, cudaFuncAttributeMaxDynamicSharedMemorySize, 33280);
    cudaFuncSetAttribute(k5_final,     cudaFuncAttributeMaxDynamicSharedMemorySize, 65536);

    k_prep_a<<<96, 256>>>(kv1w, q1w, kv2w, q2w);
    k_prep_b<<<128, 256>>>(mm1w, mm2w);
    k_prep_c<<<16, 256>>>();
    k1_pointwise<<<dim3(1024, 6, NB), 256, 33280>>>(x, y, lnw, lnb);   // profiled
    kA_stats<<<dim3(8, 4, 64), 256>>>(kvdw1, qdw1, kvdw2, qdw2);
    k_dwv<<<dim3(16, 128, NB), 256>>>(kvdw1, kvdw2);
    k4_fold<<<8, 64>>>(temp, po1, po2);
    k5_final<<<4096, 256, 65536>>>(x, y, mm1b, mm2b, out);
}